// round 2
// baseline (speedup 1.0000x reference)
#include <cuda_runtime.h>
#include <cuda_bf16.h>

// BasisEncoder: out[b][q] = ((x[b] % 256) % 64) == q ? 1.0f : 0.0f
// Since 64 divides 256 and x >= 0, idx = x[b] & 63.
// Output is 1M x 64 fp32 = 256 MB -> pure HBM store-bandwidth bound.
//
// Layout: flat float4 index j over the output (16 float4 per row).
//   row  = j >> 4       (which batch element)
//   quad = j & 15       (which group of 4 columns)
// One LDG.32 per thread (16x L1-broadcast reuse of x[row]) and one
// fully-coalesced STG.128. Branchless one-hot selection.

__global__ void __launch_bounds__(256)
basis_encoder_kernel(const int* __restrict__ x,
                     float4* __restrict__ out,
                     int total_f4) {
    int j = blockIdx.x * blockDim.x + threadIdx.x;
    if (j >= total_f4) return;

    int row  = j >> 4;        // batch index
    int quad = j & 15;        // which float4 within the 64-wide row
    int idx  = x[row] & 63;   // (x % 256) % 64 == x & 63 for x >= 0

    int base = quad << 2;
    float4 v;
    v.x = (idx == base + 0) ? 1.0f : 0.0f;
    v.y = (idx == base + 1) ? 1.0f : 0.0f;
    v.z = (idx == base + 2) ? 1.0f : 0.0f;
    v.w = (idx == base + 3) ? 1.0f : 0.0f;

    out[j] = v;
}

extern "C" void kernel_launch(void* const* d_in, const int* in_sizes, int n_in,
                              void* d_out, int out_size) {
    const int* x   = (const int*)d_in[0];
    float4*    out = (float4*)d_out;

    // out_size = BATCH * 64 floats; float4 count = out_size / 4
    int total_f4 = out_size >> 2;

    const int threads = 256;
    int blocks = (total_f4 + threads - 1) / threads;

    basis_encoder_kernel<<<blocks, threads>>>(x, out, total_f4);
}

// round 3
// speedup vs baseline: 1.0367x; 1.0367x over previous
#include <cuda_runtime.h>
#include <cuda_bf16.h>

// BasisEncoder: out[b][q] = ((x[b] & 63) == q) ? 1.0f : 0.0f
// 1M x 64 fp32 = 256 MB output -> store-stream kernel.
//
// R2 ncu: DRAM 48%, issue 25% -> latency-bound (1 dependent LDG->STG per
// thread). Fix: 8 independent tiles per thread. Block tile = 8*256 = 2048
// consecutive float4 (= 128 rows). Thread t handles flat float4 indices
// base + t + k*256, k=0..7: 8 batched LDGs of x (MLP=8), then 8 coalesced
// STG.128 with evict-streaming hint (output never re-read).

__global__ void __launch_bounds__(256)
basis_encoder_kernel(const int* __restrict__ x,
                     float4* __restrict__ out,
                     int total_f4) {
    constexpr int UNROLL = 8;
    int base = blockIdx.x * (256 * UNROLL) + threadIdx.x;

    int idx[UNROLL];
#pragma unroll
    for (int k = 0; k < UNROLL; k++) {
        int j = base + k * 256;
        // x >= 0 so (x % 256) % 64 == x & 63
        idx[k] = (j < total_f4) ? (__ldg(&x[j >> 4]) & 63) : 0;
    }

    // low 4 bits of j are threadIdx.x & 15 for all k (k*256 keeps them)
    int quad_base = (threadIdx.x & 15) << 2;

#pragma unroll
    for (int k = 0; k < UNROLL; k++) {
        int j = base + k * 256;
        if (j < total_f4) {
            float4 v;
            v.x = (idx[k] == quad_base + 0) ? 1.0f : 0.0f;
            v.y = (idx[k] == quad_base + 1) ? 1.0f : 0.0f;
            v.z = (idx[k] == quad_base + 2) ? 1.0f : 0.0f;
            v.w = (idx[k] == quad_base + 3) ? 1.0f : 0.0f;
            __stcs(&out[j], v);   // evict-streaming: never re-read
        }
    }
}

extern "C" void kernel_launch(void* const* d_in, const int* in_sizes, int n_in,
                              void* d_out, int out_size) {
    const int* x   = (const int*)d_in[0];
    float4*    out = (float4*)d_out;

    int total_f4 = out_size >> 2;          // 16,777,216 for BATCH=1M
    const int threads = 256;
    const int per_block = threads * 8;     // 2048 float4 per block
    int blocks = (total_f4 + per_block - 1) / per_block;   // 8192

    basis_encoder_kernel<<<blocks, threads>>>(x, out, total_f4);
}

// round 4
// speedup vs baseline: 1.3321x; 1.2850x over previous
#include <cuda_runtime.h>
#include <cuda_bf16.h>

// BasisEncoder: out[b][q] = ((x[b] & 63) == q) ? 1.0f : 0.0f
// 1M x 64 fp32 = 256 MB output, pure store stream.
//
// R2 (1x STG.128/thread) and R3 (8x STG.128/thread) both land ~56us,
// DRAM ~47.5%. Probe: 256-bit stores (st.global.cs.v8.f32, sm_100+) to
// halve store-instruction / wavefront count through L1tex (the only
// near-saturated unit at 79.7%).
//
// Each thread handles 32B chunks: chunk c covers cols [(c&7)*8, +8) of
// row c>>3. 8 threads share one x[row] (broadcast LDG). UNROLL=4
// independent chunks per thread for MLP.

__global__ void __launch_bounds__(256)
basis_encoder_kernel(const int* __restrict__ x,
                     float* __restrict__ out,
                     int total_chunks) {
    constexpr int UNROLL = 4;
    int base = blockIdx.x * (256 * UNROLL) + threadIdx.x;

    int d[UNROLL];
#pragma unroll
    for (int k = 0; k < UNROLL; k++) {
        int c = base + k * 256;
        int idx = (c < total_chunks) ? (__ldg(&x[c >> 3]) & 63) : -1;
        // column offset within row of this 8-float chunk: (c&7)*8.
        // (c&7) == (threadIdx.x&7) since base chunk stride is 256.
        d[k] = idx - ((threadIdx.x & 7) << 3);   // one-hot lane in [0,8) or out
    }

#pragma unroll
    for (int k = 0; k < UNROLL; k++) {
        int c = base + k * 256;
        if (c < total_chunks) {
            float v0 = (d[k] == 0) ? 1.0f : 0.0f;
            float v1 = (d[k] == 1) ? 1.0f : 0.0f;
            float v2 = (d[k] == 2) ? 1.0f : 0.0f;
            float v3 = (d[k] == 3) ? 1.0f : 0.0f;
            float v4 = (d[k] == 4) ? 1.0f : 0.0f;
            float v5 = (d[k] == 5) ? 1.0f : 0.0f;
            float v6 = (d[k] == 6) ? 1.0f : 0.0f;
            float v7 = (d[k] == 7) ? 1.0f : 0.0f;
            float* p = out + ((size_t)c << 3);
            asm volatile(
                "st.global.cs.v8.f32 [%0], {%1, %2, %3, %4, %5, %6, %7, %8};"
                :: "l"(p),
                   "f"(v0), "f"(v1), "f"(v2), "f"(v3),
                   "f"(v4), "f"(v5), "f"(v6), "f"(v7)
                : "memory");
        }
    }
}

extern "C" void kernel_launch(void* const* d_in, const int* in_sizes, int n_in,
                              void* d_out, int out_size) {
    const int* x   = (const int*)d_in[0];
    float*     out = (float*)d_out;

    int total_chunks = out_size >> 3;      // 8M chunks of 8 floats (32B)
    const int threads = 256;
    const int per_block = threads * 4;     // 1024 chunks per block
    int blocks = (total_chunks + per_block - 1) / per_block;  // 8192

    basis_encoder_kernel<<<blocks, threads>>>(x, out, total_chunks);
}

// round 5
// speedup vs baseline: 1.3643x; 1.0241x over previous
#include <cuda_runtime.h>
#include <cuda_bf16.h>
#include <cstdint>

// BasisEncoder: out[b][q] = ((x[b] & 63) == q) ? 1.0f : 0.0f
// 256 MB pure store stream.
//
// R4: v8 STG got 41.6us @ 65% DRAM -> per-thread store requests still the
// throttle. R5: stage 32KB tiles (128 rows x 64 floats) in SMEM and drain
// with one TMA bulk store per block (cp.async.bulk.global.shared::cta),
// removing the L1tex per-thread store path entirely.
//
// Fill = zero tile (8x STS.128/thread) + scatter one 1.0f per row.

static __device__ __forceinline__ uint32_t smem_u32(const void* p) {
    uint32_t a;
    asm("{ .reg .u64 t; cvta.to.shared.u64 t, %1; cvt.u32.u64 %0, t; }"
        : "=r"(a) : "l"(p));
    return a;
}

__global__ void __launch_bounds__(256)
basis_encoder_kernel(const int* __restrict__ x,
                     float* __restrict__ out) {
    __shared__ __align__(128) float tile[128 * 64];   // 32 KB

    int t = threadIdx.x;
    int row0 = blockIdx.x << 7;                        // 128 rows per block

    // 1) zero the tile: 2048 float4, 8 per thread
    float4 z = make_float4(0.f, 0.f, 0.f, 0.f);
    float4* t4 = reinterpret_cast<float4*>(tile);
#pragma unroll
    for (int k = 0; k < 8; k++)
        t4[t + k * 256] = z;
    __syncthreads();

    // 2) scatter the ones: threads 0..127 handle one row each
    if (t < 128) {
        int idx = __ldg(&x[row0 + t]) & 63;            // (x%256)%64 == x&63
        tile[(t << 6) + idx] = 1.0f;
    }
    __syncthreads();

    // 3) bulk TMA store: 32 KB SMEM -> GMEM
    if (t == 0) {
        asm volatile("fence.proxy.async.shared::cta;" ::: "memory");
        uint32_t s = smem_u32(tile);
        const float* g = out + ((size_t)row0 << 6);
        asm volatile(
            "cp.async.bulk.global.shared::cta.bulk_group [%0], [%1], %2;"
            :: "l"(g), "r"(s), "n"(128 * 64 * 4)
            : "memory");
        asm volatile("cp.async.bulk.commit_group;" ::: "memory");
        asm volatile("cp.async.bulk.wait_group.read 0;" ::: "memory");
    }
}

extern "C" void kernel_launch(void* const* d_in, const int* in_sizes, int n_in,
                              void* d_out, int out_size) {
    const int* x   = (const int*)d_in[0];
    float*     out = (float*)d_out;

    // out_size = 1048576 * 64 floats -> 8192 tiles of 128 rows
    int rows   = out_size >> 6;
    int blocks = rows >> 7;                            // exact: 8192

    basis_encoder_kernel<<<blocks, 256>>>(x, out);
}